// round 14
// baseline (speedup 1.0000x reference)
#include <cuda_runtime.h>
#include <cuda_bf16.h>

#define NLAGS   250
#define LPAD    256
#define NBLOCKS 444          // 3 CTAs/SM * 148 SMs
#define THREADS 256
#define HALF    192          // half-chunk; chunk = 2*HALF j's
#define CHUNK   (2 * HALF)   // 384
#define GG_LOG  448          // logical float2 pairs (window max = 447)
#define GG_PHYS (GG_LOG + 2 * (GG_LOG / 8))   // 560 with 2-per-8 padding

typedef unsigned long long ull;

// Deterministic reduction scratch (no allocs allowed)
__device__ float  g_partialT[LPAD * NBLOCKS];   // transposed: lag-major, contiguous per lag
__device__ float4 g_sums4[NBLOCKS];
__device__ float  g_cross[LPAD];
__device__ float4 g_tot;

static __device__ __forceinline__ void ffma2(ull& d, ull a, ull b) {
    asm("fma.rn.f32x2 %0, %1, %2, %0;" : "+l"(d) : "l"(a), "l"(b));
}
static __device__ __forceinline__ float2 unpk(ull v) {
    float lo, hi; asm("mov.b64 {%0, %1}, %2;" : "=f"(lo), "=f"(hi) : "l"(v));
    return make_float2(lo, hi);
}

// One 8-j group: window = X[0..7] ++ Y[0..7] (logical 16 pairs), P pairs broadcast.
static __device__ __forceinline__ void group8(const ull* X, const ull* Y,
                                              const ulonglong2* ppq, int pbase,
                                              ull* acc2) {
#pragma unroll
    for (int j = 0; j < 8; j += 2) {
        ulonglong2 P = ppq[pbase + (j >> 1)];   // (pair for j, pair for j+1)
#pragma unroll
        for (int k = 0; k < 8; k++) {
            const int m = j + k;
            ffma2(acc2[k], P.x, (m < 8) ? X[m] : Y[m - 8]);
        }
#pragma unroll
        for (int k = 0; k < 8; k++) {
            const int m = j + 1 + k;
            ffma2(acc2[k], P.y, (m < 8) ? X[m] : Y[m - 8]);
        }
    }
}

// ---------------------------------------------------------------------------
// Kernel A: balanced j-ranges, 384-j chunks split lo/hi (FFMA2 over halves).
// Register-prefetch double buffer hides DRAM latency; window double-buffered
// A/B with cross-group reuse; 2-per-8 float2 padding -> all LDS are 16B,
// conflict-free (80B lane stride).
// ---------------------------------------------------------------------------
__global__ void __launch_bounds__(THREADS, 3) cccorr_kernel(const float* __restrict__ p,
                                                            const float* __restrict__ g,
                                                            int T) {
    __shared__ __align__(16) float2 pp2_s[HALF];
    __shared__ __align__(16) float2 gg2_s[GG_PHYS];
    __shared__ float red[8 * LPAD];

    const int tid    = threadIdx.x;
    const int lane   = tid & 31;
    const int warpId = tid >> 5;
    const int sw     = warpId * (HALF / 8);   // warp's j-step base (24 steps)
    const int n0     = lane * 8;              // lane's base lag

    ull acc2[8];
#pragma unroll
    for (int k = 0; k < 8; k++) acc2[k] = 0ull;
    float sp = 0.f, sp2 = 0.f, sg = 0.f, sg2 = 0.f;

    // Exact balanced j-range for this block
    const long long Tll = T;
    const int r0 = (int)((Tll * blockIdx.x) / NBLOCKS);
    const int r1 = (int)((Tll * (blockIdx.x + 1)) / NBLOCKS);

    const ulonglong2* gq2 = (const ulonglong2*)gg2_s;
    const ulonglong2* ppq = (const ulonglong2*)pp2_s;
    const int i0  = sw + n0;                              // multiple of 8
    const int h   = (i0 + ((i0 >> 3) << 1)) >> 1;         // u2 index of window base
    const int pb_ = sw >> 1;                              // u2 index of p pairs

    // ---- register prefetch of one chunk ----
    float pa, pb, ga0, gb0, ga1, gb1;
    auto prefetch = [&](int c0) {
        int jl = c0 + tid;
        pa = (tid < HALF && jl < r1) ? p[jl] : 0.f;
        pb = (tid < HALF && jl + HALF < r1) ? p[jl + HALF] : 0.f;
        int x0 = c0 + tid;
        ga0 = (x0 < T) ? g[x0] : 0.f;
        gb0 = (x0 + HALF < T) ? g[x0 + HALF] : 0.f;
        int i1 = tid + THREADS;
        int x1 = c0 + i1;
        ga1 = (i1 < GG_LOG && x1 < T) ? g[x1] : 0.f;
        gb1 = (i1 < GG_LOG && x1 + HALF < T) ? g[x1 + HALF] : 0.f;
    };
    prefetch(r0);

    for (int c0 = r0; c0 < r1; c0 += CHUNK) {
        // ---- STS from regs + sums (values gated already / gate here) ----
        if (tid < HALF) {
            pp2_s[tid] = make_float2(pa, pb);
            sp += pa + pb; sp2 += pa * pa + pb * pb;
        }
        {
            int i = tid;
            gg2_s[i + ((i >> 3) << 1)] = make_float2(ga0, gb0);
            if (i < HALF) {
                if (c0 + i < r1)        { sg += ga0; sg2 += ga0 * ga0; }
                if (c0 + i + HALF < r1) { sg += gb0; sg2 += gb0 * gb0; }
            }
        }
        if (tid + THREADS < GG_LOG) {
            int i = tid + THREADS;
            gg2_s[i + ((i >> 3) << 1)] = make_float2(ga1, gb1);
        }
        __syncthreads();

        // ---- prefetch next chunk (regs free now) ----
        if (c0 + CHUNK < r1) prefetch(c0 + CHUNK);

        // ---- compute: 3 groups of 8 j's, A/B window double buffer ----
        ull A[8], B[8];
#pragma unroll
        for (int m = 0; m < 4; m++) { ulonglong2 t = gq2[h + m];      A[2*m] = t.x; A[2*m+1] = t.y; }
#pragma unroll
        for (int m = 0; m < 4; m++) { ulonglong2 t = gq2[h + 5 + m];  B[2*m] = t.x; B[2*m+1] = t.y; }
        group8(A, B, ppq, pb_, acc2);
#pragma unroll
        for (int m = 0; m < 4; m++) { ulonglong2 t = gq2[h + 10 + m]; A[2*m] = t.x; A[2*m+1] = t.y; }
        group8(B, A, ppq, pb_ + 4, acc2);
#pragma unroll
        for (int m = 0; m < 4; m++) { ulonglong2 t = gq2[h + 15 + m]; B[2*m] = t.x; B[2*m+1] = t.y; }
        group8(A, B, ppq, pb_ + 8, acc2);

        __syncthreads();
    }

    // Unpack (lo+hi = both halves) + reduce 8 warps per lag -> transposed partials
#pragma unroll
    for (int k = 0; k < 8; k++) {
        float2 v = unpk(acc2[k]);
        red[warpId * LPAD + n0 + k] = v.x + v.y;
    }
    __syncthreads();
    {
        float s = 0.f;
#pragma unroll
        for (int w = 0; w < 8; w++) s += red[w * LPAD + tid];
        g_partialT[tid * NBLOCKS + blockIdx.x] = s;
    }

    // Reduce the 4 scalar sums
#pragma unroll
    for (int off = 16; off; off >>= 1) {
        sp  += __shfl_down_sync(0xFFFFFFFFu, sp,  off);
        sp2 += __shfl_down_sync(0xFFFFFFFFu, sp2, off);
        sg  += __shfl_down_sync(0xFFFFFFFFu, sg,  off);
        sg2 += __shfl_down_sync(0xFFFFFFFFu, sg2, off);
    }
    __shared__ float sred[8][4];
    if (lane == 0) {
        sred[warpId][0] = sp;  sred[warpId][1] = sp2;
        sred[warpId][2] = sg;  sred[warpId][3] = sg2;
    }
    __syncthreads();
    if (tid < 4) {
        float t = 0.f;
#pragma unroll
        for (int w = 0; w < 8; w++) t += sred[w][tid];
        ((float*)&g_sums4[blockIdx.x])[tid] = t;
    }
}

// ---------------------------------------------------------------------------
// Kernel B1: grid-parallel reduction. Blocks 0..249 reduce one lag each
// (444 contiguous floats, coalesced). Block 250 reduces the float4 sums.
// ---------------------------------------------------------------------------
#define B1_THREADS 128

__global__ void __launch_bounds__(B1_THREADS) reduce_kernel() {
    const int t    = threadIdx.x;
    const int lane = t & 31;
    const int wp   = t >> 5;
    const int lag  = blockIdx.x;

    if (lag < NLAGS) {
        const float* base = g_partialT + lag * NBLOCKS;
        float s = base[t] + base[t + B1_THREADS] + base[t + 2 * B1_THREADS];  // 384
        if (t < NBLOCKS - 3 * B1_THREADS) s += base[3 * B1_THREADS + t];      // +60
#pragma unroll
        for (int off = 16; off; off >>= 1) s += __shfl_down_sync(0xFFFFFFFFu, s, off);
        __shared__ float ws[4];
        if (lane == 0) ws[wp] = s;
        __syncthreads();
        if (t == 0) g_cross[lag] = (ws[0] + ws[1]) + (ws[2] + ws[3]);
    } else {
        // block 250: reduce g_sums4
        float x = 0.f, y = 0.f, z = 0.f, w = 0.f;
        for (int i = t; i < NBLOCKS; i += B1_THREADS) {
            float4 v = g_sums4[i];
            x += v.x; y += v.y; z += v.z; w += v.w;
        }
#pragma unroll
        for (int off = 16; off; off >>= 1) {
            x += __shfl_down_sync(0xFFFFFFFFu, x, off);
            y += __shfl_down_sync(0xFFFFFFFFu, y, off);
            z += __shfl_down_sync(0xFFFFFFFFu, z, off);
            w += __shfl_down_sync(0xFFFFFFFFu, w, off);
        }
        __shared__ float4 ws4[4];
        if (lane == 0) ws4[wp] = make_float4(x, y, z, w);
        __syncthreads();
        if (t == 0) {
            float4 a = ws4[0], b = ws4[1], c = ws4[2], d = ws4[3];
            g_tot = make_float4((a.x + b.x) + (c.x + d.x),
                                (a.y + b.y) + (c.y + d.y),
                                (a.z + b.z) + (c.z + d.z),
                                (a.w + b.w) + (c.w + d.w));
        }
    }
}

// ---------------------------------------------------------------------------
// Kernel B2: tiny finalize. Tail scan + per-lag CCC + scalar output.
// ---------------------------------------------------------------------------
__global__ void __launch_bounds__(LPAD) finalize_kernel(const float* __restrict__ p,
                                                        int T,
                                                        float* __restrict__ out) {
    __shared__ float scanA[LPAD], scanB[LPAD];
    __shared__ float scan2A[LPAD], scan2B[LPAD];
    __shared__ float cccs[LPAD];

    const int tid = threadIdx.x;
    {
        float v = (tid >= 1) ? p[T - tid] : 0.f;
        scanA[tid]  = v;
        scan2A[tid] = v * v;
    }
    __syncthreads();
#pragma unroll
    for (int s = 0; s < 8; s++) {
        int off = 1 << s;
        float a  = scanA[tid]  + ((tid >= off) ? scanA[tid - off]  : 0.f);
        float a2 = scan2A[tid] + ((tid >= off) ? scan2A[tid - off] : 0.f);
        __syncthreads();
        scanB[tid] = a; scan2B[tid] = a2;
        __syncthreads();
        scanA[tid] = scanB[tid]; scan2A[tid] = scan2B[tid];
        __syncthreads();
    }

    const float4 tot = g_tot;
    const float Sp  = tot.x, Sp2 = tot.y;
    const float Sg  = tot.z, Sg2 = tot.w;
    const float Tf  = (float)T;
    const float mean_gt = Sg / Tf;
    const float var_gt  = (Sg2 - Tf * mean_gt * mean_gt) / (Tf - 1.f);

    float ccc = 0.f;
    if (tid < NLAGS) {
        float cross = g_cross[tid];
        float Spn   = Sp  - scanA[tid];
        float Spn2  = Sp2 - scan2A[tid];
        float mean_pred = Spn / Tf;
        float var_pred  = (Spn2 - Tf * mean_pred * mean_pred) / (Tf - 1.f);
        float cov = (cross - mean_gt * Spn) / Tf;
        float dm  = mean_gt - mean_pred;
        float denom = var_gt + var_pred + dm * dm;
        ccc = 2.f * cov / denom;
    }
    cccs[tid] = ccc;
    __syncthreads();
#pragma unroll
    for (int off = LPAD / 2; off >= 1; off >>= 1) {
        if (tid < off) cccs[tid] += cccs[tid + off];
        __syncthreads();
    }
    if (tid == 0) out[0] = 1.f - cccs[0] / (float)NLAGS;
}

extern "C" void kernel_launch(void* const* d_in, const int* in_sizes, int n_in,
                              void* d_out, int out_size) {
    const float* pred = (const float*)d_in[0];
    const float* gt   = (const float*)d_in[1];
    float* out = (float*)d_out;
    int T = in_sizes[0];

    cccorr_kernel<<<NBLOCKS, THREADS>>>(pred, gt, T);
    reduce_kernel<<<NLAGS + 1, B1_THREADS>>>();
    finalize_kernel<<<1, LPAD>>>(pred, T, out);
}

// round 16
// speedup vs baseline: 1.0865x; 1.0865x over previous
#include <cuda_runtime.h>
#include <cuda_bf16.h>

#define NLAGS   250
#define LPAD    256
#define NBLOCKS 444          // 3 CTAs/SM * 148 SMs = exactly one wave
#define THREADS 256
#define HALF    192          // half-chunk; chunk = 2*HALF j's
#define CHUNK   (2 * HALF)   // 384
#define GG_LOG  448          // logical float2 pairs (window max = 447)
#define GG_PHYS (GG_LOG + 2 * (GG_LOG / 8))   // 560 with 2-per-8 padding

typedef unsigned long long ull;

// Deterministic reduction scratch (no allocs allowed)
__device__ float  g_partialT[LPAD * NBLOCKS];   // transposed: lag-major, contiguous per lag
__device__ float4 g_sums4[NBLOCKS];
__device__ float  g_ccc[NLAGS];
__device__ float4 g_tot;
__device__ unsigned int g_ctr1 = 0;
__device__ unsigned int g_ctr2 = 0;

static __device__ __forceinline__ void ffma2(ull& d, ull a, ull b) {
    asm("fma.rn.f32x2 %0, %1, %2, %0;" : "+l"(d) : "l"(a), "l"(b));
}
static __device__ __forceinline__ float2 unpk(ull v) {
    float lo, hi; asm("mov.b64 {%0, %1}, %2;" : "=f"(lo), "=f"(hi) : "l"(v));
    return make_float2(lo, hi);
}

// One 8-j group: window = X[0..7] ++ Y[0..7] (logical 16 pairs), P pairs broadcast.
static __device__ __forceinline__ void group8(const ull* X, const ull* Y,
                                              const ulonglong2* ppq, int pbase,
                                              ull* acc2) {
#pragma unroll
    for (int j = 0; j < 8; j += 2) {
        ulonglong2 P = ppq[pbase + (j >> 1)];   // (pair for j, pair for j+1)
#pragma unroll
        for (int k = 0; k < 8; k++) {
            const int m = j + k;
            ffma2(acc2[k], P.x, (m < 8) ? X[m] : Y[m - 8]);
        }
#pragma unroll
        for (int k = 0; k < 8; k++) {
            const int m = j + 1 + k;
            ffma2(acc2[k], P.y, (m < 8) ? X[m] : Y[m - 8]);
        }
    }
}

// ---------------------------------------------------------------------------
// Kernel A: balanced j-ranges, 384-j chunks split lo/hi (FFMA2 over halves).
// Register-prefetch double buffer hides DRAM latency; window double-buffered
// A/B with cross-group reuse; 2-per-8 float2 padding -> all LDS are 16B,
// conflict-free. Last block (fence+counter) reduces g_sums4 -> g_tot.
// ---------------------------------------------------------------------------
__global__ void __launch_bounds__(THREADS, 3) cccorr_kernel(const float* __restrict__ p,
                                                            const float* __restrict__ g,
                                                            int T) {
    __shared__ __align__(16) float2 pp2_s[HALF];
    __shared__ __align__(16) float2 gg2_s[GG_PHYS];
    __shared__ float red[8 * LPAD];

    const int tid    = threadIdx.x;
    const int lane   = tid & 31;
    const int warpId = tid >> 5;
    const int sw     = warpId * (HALF / 8);   // warp's j-step base (24 steps)
    const int n0     = lane * 8;              // lane's base lag

    ull acc2[8];
#pragma unroll
    for (int k = 0; k < 8; k++) acc2[k] = 0ull;
    float sp = 0.f, sp2 = 0.f, sg = 0.f, sg2 = 0.f;

    // Exact balanced j-range for this block
    const long long Tll = T;
    const int r0 = (int)((Tll * blockIdx.x) / NBLOCKS);
    const int r1 = (int)((Tll * (blockIdx.x + 1)) / NBLOCKS);

    const ulonglong2* gq2 = (const ulonglong2*)gg2_s;
    const ulonglong2* ppq = (const ulonglong2*)pp2_s;
    const int i0  = sw + n0;                              // multiple of 8
    const int h   = (i0 + ((i0 >> 3) << 1)) >> 1;         // u2 index of window base
    const int pb_ = sw >> 1;                              // u2 index of p pairs

    // ---- register prefetch of one chunk ----
    float pa, pb, ga0, gb0, ga1, gb1;
    auto prefetch = [&](int c0) {
        int jl = c0 + tid;
        pa = (tid < HALF && jl < r1) ? p[jl] : 0.f;
        pb = (tid < HALF && jl + HALF < r1) ? p[jl + HALF] : 0.f;
        int x0 = c0 + tid;
        ga0 = (x0 < T) ? g[x0] : 0.f;
        gb0 = (x0 + HALF < T) ? g[x0 + HALF] : 0.f;
        int i1 = tid + THREADS;
        int x1 = c0 + i1;
        ga1 = (i1 < GG_LOG && x1 < T) ? g[x1] : 0.f;
        gb1 = (i1 < GG_LOG && x1 + HALF < T) ? g[x1 + HALF] : 0.f;
    };
    prefetch(r0);

    for (int c0 = r0; c0 < r1; c0 += CHUNK) {
        // ---- STS from regs + sums ----
        if (tid < HALF) {
            pp2_s[tid] = make_float2(pa, pb);
            sp += pa + pb; sp2 += pa * pa + pb * pb;
        }
        {
            int i = tid;
            gg2_s[i + ((i >> 3) << 1)] = make_float2(ga0, gb0);
            if (i < HALF) {
                if (c0 + i < r1)        { sg += ga0; sg2 += ga0 * ga0; }
                if (c0 + i + HALF < r1) { sg += gb0; sg2 += gb0 * gb0; }
            }
        }
        if (tid + THREADS < GG_LOG) {
            int i = tid + THREADS;
            gg2_s[i + ((i >> 3) << 1)] = make_float2(ga1, gb1);
        }
        __syncthreads();

        // ---- prefetch next chunk (regs free now) ----
        if (c0 + CHUNK < r1) prefetch(c0 + CHUNK);

        // ---- compute: 3 groups of 8 j's, A/B window double buffer ----
        ull A[8], B[8];
#pragma unroll
        for (int m = 0; m < 4; m++) { ulonglong2 t = gq2[h + m];      A[2*m] = t.x; A[2*m+1] = t.y; }
#pragma unroll
        for (int m = 0; m < 4; m++) { ulonglong2 t = gq2[h + 5 + m];  B[2*m] = t.x; B[2*m+1] = t.y; }
        group8(A, B, ppq, pb_, acc2);
#pragma unroll
        for (int m = 0; m < 4; m++) { ulonglong2 t = gq2[h + 10 + m]; A[2*m] = t.x; A[2*m+1] = t.y; }
        group8(B, A, ppq, pb_ + 4, acc2);
#pragma unroll
        for (int m = 0; m < 4; m++) { ulonglong2 t = gq2[h + 15 + m]; B[2*m] = t.x; B[2*m+1] = t.y; }
        group8(A, B, ppq, pb_ + 8, acc2);

        __syncthreads();
    }

    // Unpack (lo+hi = both halves) + reduce 8 warps per lag -> transposed partials
#pragma unroll
    for (int k = 0; k < 8; k++) {
        float2 v = unpk(acc2[k]);
        red[warpId * LPAD + n0 + k] = v.x + v.y;
    }
    __syncthreads();
    {
        float s = 0.f;
#pragma unroll
        for (int w = 0; w < 8; w++) s += red[w * LPAD + tid];
        g_partialT[tid * NBLOCKS + blockIdx.x] = s;
    }

    // Reduce the 4 scalar sums -> g_sums4[block]
#pragma unroll
    for (int off = 16; off; off >>= 1) {
        sp  += __shfl_down_sync(0xFFFFFFFFu, sp,  off);
        sp2 += __shfl_down_sync(0xFFFFFFFFu, sp2, off);
        sg  += __shfl_down_sync(0xFFFFFFFFu, sg,  off);
        sg2 += __shfl_down_sync(0xFFFFFFFFu, sg2, off);
    }
    __shared__ float sred[8][4];
    if (lane == 0) {
        sred[warpId][0] = sp;  sred[warpId][1] = sp2;
        sred[warpId][2] = sg;  sred[warpId][3] = sg2;
    }
    __syncthreads();
    if (tid < 4) {
        float t = 0.f;
#pragma unroll
        for (int w = 0; w < 8; w++) t += sred[w][tid];
        ((float*)&g_sums4[blockIdx.x])[tid] = t;
    }

    // ---- last block reduces g_sums4 -> g_tot (deterministic, self-resetting) ----
    __threadfence();
    __shared__ unsigned s_last;
    if (tid == 0) s_last = (atomicAdd(&g_ctr1, 1u) == NBLOCKS - 1u) ? 1u : 0u;
    __syncthreads();
    if (s_last) {
        float x = 0.f, y = 0.f, z = 0.f, w = 0.f;
        for (int i = tid; i < NBLOCKS; i += THREADS) {
            float4 v = g_sums4[i];
            x += v.x; y += v.y; z += v.z; w += v.w;
        }
#pragma unroll
        for (int off = 16; off; off >>= 1) {
            x += __shfl_down_sync(0xFFFFFFFFu, x, off);
            y += __shfl_down_sync(0xFFFFFFFFu, y, off);
            z += __shfl_down_sync(0xFFFFFFFFu, z, off);
            w += __shfl_down_sync(0xFFFFFFFFu, w, off);
        }
        __shared__ float4 w4[8];
        if (lane == 0) w4[warpId] = make_float4(x, y, z, w);
        __syncthreads();
        if (tid == 0) {
            float4 t = make_float4(0.f, 0.f, 0.f, 0.f);
#pragma unroll
            for (int u = 0; u < 8; u++) {
                t.x += w4[u].x; t.y += w4[u].y; t.z += w4[u].z; t.w += w4[u].w;
            }
            g_tot = t;
            g_ctr1 = 0;   // reset for next graph replay
        }
    }
}

// ---------------------------------------------------------------------------
// Kernel B: 250 blocks. Block `lag` computes cross[lag], its tail prefix,
// and ccc[lag]; the last block averages all cccs and writes the output.
// ---------------------------------------------------------------------------
__global__ void __launch_bounds__(THREADS) finalize2_kernel(const float* __restrict__ p,
                                                            int T,
                                                            float* __restrict__ out) {
    const int lag  = blockIdx.x;
    const int tid  = threadIdx.x;
    const int lane = tid & 31;
    const int wp   = tid >> 5;

    // cross[lag]: 444 contiguous floats
    float s = 0.f;
    const float* base = g_partialT + lag * NBLOCKS;
    for (int i = tid; i < NBLOCKS; i += THREADS) s += base[i];

    // tail: sum_{k=1..lag} p[T-k] (thread t holds k=t)
    float tp = 0.f, tp2 = 0.f;
    if (tid >= 1 && tid <= lag) {
        float v = p[T - tid];
        tp = v; tp2 = v * v;
    }

    // block-reduce (s, tp, tp2)
#pragma unroll
    for (int off = 16; off; off >>= 1) {
        s   += __shfl_down_sync(0xFFFFFFFFu, s,   off);
        tp  += __shfl_down_sync(0xFFFFFFFFu, tp,  off);
        tp2 += __shfl_down_sync(0xFFFFFFFFu, tp2, off);
    }
    __shared__ float r3[8][3];
    if (lane == 0) { r3[wp][0] = s; r3[wp][1] = tp; r3[wp][2] = tp2; }
    __syncthreads();
    if (tid == 0) {
        float cross = 0.f, tps = 0.f, tp2s = 0.f;
#pragma unroll
        for (int u = 0; u < 8; u++) { cross += r3[u][0]; tps += r3[u][1]; tp2s += r3[u][2]; }

        const float4 tot = g_tot;
        const float Sp  = tot.x, Sp2 = tot.y;
        const float Sg  = tot.z, Sg2 = tot.w;
        const float Tf  = (float)T;
        const float mean_gt = Sg / Tf;
        const float var_gt  = (Sg2 - Tf * mean_gt * mean_gt) / (Tf - 1.f);

        float Spn  = Sp  - tps;            // sum of p[0 : T-n]
        float Spn2 = Sp2 - tp2s;
        float mean_pred = Spn / Tf;
        float var_pred  = (Spn2 - Tf * mean_pred * mean_pred) / (Tf - 1.f);
        float cov = (cross - mean_gt * Spn) / Tf;
        float dm  = mean_gt - mean_pred;
        g_ccc[lag] = 2.f * cov / (var_gt + var_pred + dm * dm);
    }

    // last block averages the cccs
    __threadfence();
    __shared__ unsigned s_last;
    if (tid == 0) s_last = (atomicAdd(&g_ctr2, 1u) == NLAGS - 1u) ? 1u : 0u;
    __syncthreads();
    if (s_last) {
        float c = (tid < NLAGS) ? g_ccc[tid] : 0.f;
#pragma unroll
        for (int off = 16; off; off >>= 1) c += __shfl_down_sync(0xFFFFFFFFu, c, off);
        __shared__ float cs[8];
        if (lane == 0) cs[wp] = c;
        __syncthreads();
        if (tid == 0) {
            float t = 0.f;
#pragma unroll
            for (int u = 0; u < 8; u++) t += cs[u];
            out[0] = 1.f - t / (float)NLAGS;
            g_ctr2 = 0;   // reset for next graph replay
        }
    }
}

extern "C" void kernel_launch(void* const* d_in, const int* in_sizes, int n_in,
                              void* d_out, int out_size) {
    const float* pred = (const float*)d_in[0];
    const float* gt   = (const float*)d_in[1];
    float* out = (float*)d_out;
    int T = in_sizes[0];

    cccorr_kernel<<<NBLOCKS, THREADS>>>(pred, gt, T);
    finalize2_kernel<<<NLAGS, THREADS>>>(pred, T, out);
}